// round 5
// baseline (speedup 1.0000x reference)
#include <cuda_runtime.h>
#include <math.h>

#define NBATCH 64
#define NANC   3
#define NCLS   13
#define NHH    76
#define NWW    76
#define NPIX   (NHH*NWW)          // 5776
#define NANCH  (NANC*NPIX)        // 17328
#define MAXT   50
#define NLV    12
#define NCH    (NLV+NCLS)         // 25
#define BETA_C 0.028f
#define NETWH  608.0f

#define GRP8PB  (NANCH/8)         // 2166 groups of 8 cells per batch
#define DBPB    9                 // dense blocks per batch
#define GPBLK   241               // groups per dense block (241*9=2169 >= 2166)
#define DBLKS   (NBATCH*DBPB)     // 576 dense blocks
#define NBLKS   (DBLKS+NBATCH)    // 640 total blocks

// -------- persistent scratch (zero-initialized; self-resetting) --------
__device__ double   g_acc;
__device__ unsigned g_done;

__device__ __forceinline__ float softplusf(float x) {
    return fmaxf(x, 0.f) + __logf(1.f + __expf(-fabsf(x)));
}
__device__ __forceinline__ float bce_logit(float x, float t) {
    return softplusf(x) - t * x;      // == bce(sigmoid(x), t)
}
__device__ __forceinline__ float sigfast(float x) {
    return 1.f / (1.f + __expf(-x));
}

__device__ __forceinline__ bool cell_ignored(
    float o0, float o1, float o9, float o10, float aw, float ah,
    int i, int j, int cnt, const float4* lh, const float* ga)
{
    float pw = __expf(o9) * aw, ph = __expf(o10) * ah;
    float px = sigfast(o0) + (float)i;
    float py = sigfast(o1) + (float)j;
    float pxlo = px - 0.5f*pw, pxhi = px + 0.5f*pw;
    float pylo = py - 0.5f*ph, pyhi = py + 0.5f*ph;
    float pa = pw * ph;
    bool ig = false;
    for (int k = 0; k < cnt; k++) {
        float cw = fminf(pxhi, lh[k].y) - fmaxf(pxlo, lh[k].x);
        float ch = fminf(pyhi, lh[k].w) - fmaxf(pylo, lh[k].z);
        float inter = fmaxf(cw, 0.f) * fmaxf(ch, 0.f);
        if (3.f*inter > pa + ga[k]) ig = true;     // iou > 0.5
    }
    return ig;
}

__device__ __forceinline__ float iou_div(float x1,float y1,float w1,float h1,
                                         float x2,float y2,float w2,float h2) {
    float cw = fminf(x1+0.5f*w1, x2+0.5f*w2) - fmaxf(x1-0.5f*w1, x2-0.5f*w2);
    float ch = fminf(y1+0.5f*h1, y2+0.5f*h2) - fmaxf(y1-0.5f*h1, y2-0.5f*h2);
    float inter = (cw > 0.f && ch > 0.f) ? cw*ch : 0.f;
    return inter / (w1*h1 + w2*h2 - inter);
}

__global__ void __launch_bounds__(256, 4)
k_fused(const float* __restrict__ out,
        const float* __restrict__ tgt,
        const float* __restrict__ anch,
        float* __restrict__ d_out)
{
    __shared__ float    st[MAXT*12];
    __shared__ float4   s_lh[MAXT];
    __shared__ float    s_ga[MAXT];
    __shared__ int      s_flat[MAXT];
    __shared__ int      s_cls[MAXT];
    __shared__ float    s_anc[6];
    __shared__ float    s_gm;
    __shared__ int      s_cnt;
    __shared__ unsigned s_m0, s_m1;
    __shared__ double   s_wsum[8];

    int tid = threadIdx.x;
    if (tid < 6) s_anc[tid] = anch[tid];
    double local = 0.0;

    if (blockIdx.x < DBLKS) {
        // ============ dense role: noobj loss, 8 cells/thread, loads batched ============
        int b = blockIdx.x / DBPB;
        int part = blockIdx.x - b*DBPB;

        bool pos = false;
        if (tid < MAXT) {
            const float* p = tgt + b*MAXT*12 + tid*12;
            float x = p[1], y = p[2];
            float gw = p[10]*NETWH, gh = p[11]*NETWH;
            float gx = x*(float)NWW, gy = y*(float)NHH;
            s_lh[tid] = make_float4(gx-0.5f*gw, gx+0.5f*gw, gy-0.5f*gh, gy+0.5f*gh);
            s_ga[tid] = gw*gh;
            pos = (x > 0.f);
        }
        if (tid < 64) {
            unsigned bal = __ballot_sync(0xFFFFFFFFu, pos);
            if ((tid & 31) == 0) { if (tid < 32) s_m0 = bal; else s_m1 = bal; }
        }
        __syncthreads();
        if (tid == 0) {
            int c = (~s_m0) ? (__ffs(~s_m0) - 1) : (32 + __ffs(~s_m1) - 1);
            if (c > MAXT) c = MAXT;
            float gm = 1e30f;
            for (int k = 0; k < c; k++) gm = fminf(gm, s_ga[k]);
            s_cnt = c; s_gm = gm;
        }
        __syncthreads();
        int   cnt = s_cnt;
        float gm  = s_gm;

        float lf = 0.f;
        int g8 = part*GPBLK + tid;
        if (tid < GPBLK && g8 < GRP8PB) {
            int cell0 = g8 * 8;                       // 8-aligned, never crosses anchor
            int a = (cell0 >= 2*NPIX) ? 2 : (cell0 >= NPIX ? 1 : 0);
            int rem = cell0 - a*NPIX;
            const float* basep = out + (size_t)(b*NANC + a)*NCH*NPIX + rem;
            float aw = s_anc[2*a], ah = s_anc[2*a+1];
            float awah = aw*ah;

            // 6 independent 16B loads, front-batched (MLP=6)
            const float4* p9  = reinterpret_cast<const float4*>(basep + 9*NPIX);
            const float4* p10 = reinterpret_cast<const float4*>(basep + 10*NPIX);
            const float4* p11 = reinterpret_cast<const float4*>(basep + 11*NPIX);
            float4 v9a  = p9[0],  v9b  = p9[1];
            float4 v10a = p10[0], v10b = p10[1];
            float4 v11a = p11[0], v11b = p11[1];

            float a9[8]  = {v9a.x,v9a.y,v9a.z,v9a.w,   v9b.x,v9b.y,v9b.z,v9b.w};
            float a10[8] = {v10a.x,v10a.y,v10a.z,v10a.w,v10b.x,v10b.y,v10b.z,v10b.w};
            float a11[8] = {v11a.x,v11a.y,v11a.z,v11a.w,v11b.x,v11b.y,v11b.z,v11b.w};

            #pragma unroll
            for (int s = 0; s < 8; s++) {
                float o9 = a9[s], o10 = a10[s], o11 = a11[s];
                float pa_gate = awah * __expf(o9 + o10);
                bool ig = false;
                if (2.f*pa_gate > 0.99f*gm) {
                    float o0 = basep[s];
                    float o1 = basep[NPIX + s];
                    int cell = rem + s;
                    int j = cell / NWW;
                    int i = cell - j*NWW;
                    ig = cell_ignored(o0, o1, o9, o10, aw, ah, i, j,
                                      cnt, s_lh, s_ga);
                }
                if (!ig) lf += softplusf(o11);
            }
        }
        local = (double)lf;
    } else {
        // ============ target role: obj-cell losses for one batch ============
        int b = blockIdx.x - DBLKS;
        for (int i = tid; i < MAXT*12; i += 256) st[i] = tgt[b*MAXT*12 + i];
        __syncthreads();

        int t = tid;
        bool pos = (t < MAXT) && (st[t*12 + 1] > 0.f);
        if (t < 64) {
            unsigned bal = __ballot_sync(0xFFFFFFFFu, pos);
            if ((t & 31) == 0) { if (t < 32) s_m0 = bal; else s_m1 = bal; }
        }
        __syncthreads();
        if (t == 0) {
            int c = (~s_m0) ? (__ffs(~s_m0) - 1) : (32 + __ffs(~s_m1) - 1);
            if (c > MAXT) c = MAXT;
            s_cnt = c;
        }
        __syncthreads();
        int cnt = s_cnt;

        float gx=0, gy=0, gw=0, gh=0, aw=0, ah=0;
        int best=0, gi=0, gj=0, flat=-1;
        if (t < MAXT) {
            const float* tb = st + t*12;
            gx = tb[1]*(float)NWW;  gy = tb[2]*(float)NHH;
            gw = tb[10]*NETWH;      gh = tb[11]*NETWH;
            s_ga[t] = gw*gh;
            s_lh[t] = make_float4(gx-0.5f*gw, gx+0.5f*gw, gy-0.5f*gh, gy+0.5f*gh);
            if (t < cnt) {
                float bestr = -1.f;
                #pragma unroll
                for (int a = 0; a < NANC; a++) {
                    float aw_ = s_anc[2*a], ah_ = s_anc[2*a+1];
                    float inter = fminf(gw, aw_) * fminf(gh, ah_);
                    float r = inter / (gw*gh + aw_*ah_ - inter);
                    if (r > bestr) { bestr = r; best = a; }
                }
                gi = min(max((int)floorf(gx), 0), NWW-1);
                gj = min(max((int)floorf(gy), 0), NHH-1);
                flat = best*NPIX + gj*NWW + gi;
                aw = s_anc[2*best]; ah = s_anc[2*best+1];
            }
            s_flat[t] = flat;
            s_cls[t]  = (int)tb[0];
        }
        __syncthreads();
        if (t == 0) {
            float gm = 1e30f;
            for (int k = 0; k < cnt; k++) gm = fminf(gm, s_ga[k]);
            s_gm = gm;
        }
        __syncthreads();

        if (t < cnt) {
            bool winner = true; unsigned mask = 0;
            for (int t2 = 0; t2 < cnt; t2++) {
                if (s_flat[t2] == flat) {
                    if (t2 > t) winner = false;
                    mask |= 1u << s_cls[t2];
                }
            }
            if (winner) {
                const float* tb = st + t*12;
                const float* basep = out + (size_t)(b*NANC + best)*NCH*NPIX
                                         + (gj*NWW + gi);
                float o[12];
                #pragma unroll
                for (int c = 0; c < 12; c++) o[c] = basep[c*NPIX];
                float cl[NCLS];
                #pragma unroll
                for (int c = 0; c < NCLS; c++) cl[c] = basep[(NLV + c)*NPIX];

                float l = 0.f;
                float tx = gx - (float)gi, ty = gy - (float)gj;
                l += bce_logit(o[0], tx) + bce_logit(o[1], ty);
                float r9 = logf(gw/aw), r10 = logf(gh/ah);
                float d9 = o[9]-r9, d10 = o[10]-r10;
                l += d9*d9 + d10*d10;
                float d2 = o[2]-tb[3], d3 = o[3]-tb[4], d4 = o[4]-tb[5];
                float ss = d2*d2 + d3*d3 + d4*d4;
                float dis = sqrtf(ss);
                if (dis <= BETA_C) l += 0.5f*ss/BETA_C;
                else               l += fabsf(d2)+fabsf(d3)+fabsf(d4) - 0.5f*BETA_C;
                float nrm = fmaxf(sqrtf(o[5]*o[5]+o[6]*o[6]+o[7]*o[7]+o[8]*o[8]), 1e-12f);
                l += fabsf(o[5]/nrm - tb[6]) + fabsf(o[6]/nrm - tb[7])
                   + fabsf(o[7]/nrm - tb[8]) + fabsf(o[8]/nrm - tb[9]);
                float px = sigfast(o[0]) + (float)gi;
                float py = sigfast(o[1]) + (float)gj;
                float pw = __expf(o[9])*aw, ph = __expf(o[10])*ah;
                float iou_t = iou_div(gx, gy, gw, gh, px, py, pw, ph);
                l += bce_logit(o[11], iou_t);
                #pragma unroll
                for (int c = 0; c < NCLS; c++) {
                    float tt = ((mask >> c) & 1u) ? 1.f : 0.f;
                    l += bce_logit(cl[c], tt);
                }
                // subtract the dense role's noobj contribution for this cell
                float pa_gate = aw*ah*__expf(o[9]+o[10]);
                bool ig = false;
                if (2.f*pa_gate > 0.99f*s_gm)
                    ig = cell_ignored(o[0], o[1], o[9], o[10], aw, ah, gi, gj,
                                      cnt, s_lh, s_ga);
                if (!ig) l -= softplusf(o[11]);
                local = (double)l;
            }
        }
    }

    // ============ common block reduction + last-block finalize ============
    #pragma unroll
    for (int off = 16; off > 0; off >>= 1)
        local += __shfl_down_sync(0xFFFFFFFFu, local, off);
    int lane = tid & 31, wid = tid >> 5;
    if (lane == 0) s_wsum[wid] = local;
    __syncthreads();
    if (tid == 0) {
        double bs = 0.0;
        #pragma unroll
        for (int w = 0; w < 8; w++) bs += s_wsum[w];
        atomicAdd(&g_acc, bs);
        __threadfence();
        unsigned old = atomicAdd(&g_done, 1u);
        if (old == NBLKS - 1) {
            double tot = atomicAdd(&g_acc, 0.0);   // ordered read
            d_out[0] = (float)(tot * (1.0/(double)NBATCH));
            g_acc = 0.0;                           // self-reset for graph replay
            __threadfence();
            g_done = 0u;
        }
    }
}

extern "C" void kernel_launch(void* const* d_in, const int* in_sizes, int n_in,
                              void* d_out, int out_size) {
    const float* out  = nullptr;
    const float* tgt  = nullptr;
    const float* anch = nullptr;
    for (int k = 0; k < n_in; k++) {
        if      (in_sizes[k] == NBATCH*NANC*NCH*NPIX) out  = (const float*)d_in[k];
        else if (in_sizes[k] == NBATCH*MAXT*NLV)      tgt  = (const float*)d_in[k];
        else if (in_sizes[k] == NANC*2)               anch = (const float*)d_in[k];
    }
    k_fused<<<NBLKS, 256>>>(out, tgt, anch, (float*)d_out);
}

// round 7
// speedup vs baseline: 1.1572x; 1.1572x over previous
#include <cuda_runtime.h>
#include <math.h>

#define NBATCH 64
#define NANC   3
#define NCLS   13
#define NHH    76
#define NWW    76
#define NPIX   (NHH*NWW)          // 5776
#define NANCH  (NANC*NPIX)        // 17328
#define MAXT   50
#define NLV    12
#define NCH    (NLV+NCLS)         // 25
#define BETA_C 0.028f
#define NETWH  608.0f

#define GPB_TOT (NANCH/4)         // 4332 coalesced 4-cell groups per batch
#define DBPB    8                 // dense blocks per batch
#define GPBLK   542               // groups per dense block (542*8=4336 >= 4332)
#define DBLKS   (NBATCH*DBPB)     // 512 dense blocks
#define NBLKS   (DBLKS+NBATCH)    // 576 total blocks

// -------- persistent scratch (zero-initialized; self-resetting) --------
__device__ double   g_acc;
__device__ unsigned g_done;

__device__ __forceinline__ float softplusf(float x) {
    return fmaxf(x, 0.f) + __logf(1.f + __expf(-fabsf(x)));
}
__device__ __forceinline__ float bce_logit(float x, float t) {
    return softplusf(x) - t * x;      // == bce(sigmoid(x), t)
}
__device__ __forceinline__ float sigfast(float x) {
    return 1.f / (1.f + __expf(-x));
}

__device__ __forceinline__ bool cell_ignored(
    float o0, float o1, float o9, float o10, float aw, float ah,
    int i, int j, int cnt, const float4* lh, const float* ga)
{
    float pw = __expf(o9) * aw, ph = __expf(o10) * ah;
    float px = sigfast(o0) + (float)i;
    float py = sigfast(o1) + (float)j;
    float pxlo = px - 0.5f*pw, pxhi = px + 0.5f*pw;
    float pylo = py - 0.5f*ph, pyhi = py + 0.5f*ph;
    float pa = pw * ph;
    bool ig = false;
    for (int k = 0; k < cnt; k++) {
        float cw = fminf(pxhi, lh[k].y) - fmaxf(pxlo, lh[k].x);
        float ch = fminf(pyhi, lh[k].w) - fmaxf(pylo, lh[k].z);
        float inter = fmaxf(cw, 0.f) * fmaxf(ch, 0.f);
        if (3.f*inter > pa + ga[k]) ig = true;     // iou > 0.5
    }
    return ig;
}

__device__ __forceinline__ float iou_div(float x1,float y1,float w1,float h1,
                                         float x2,float y2,float w2,float h2) {
    float cw = fminf(x1+0.5f*w1, x2+0.5f*w2) - fmaxf(x1-0.5f*w1, x2-0.5f*w2);
    float ch = fminf(y1+0.5f*h1, y2+0.5f*h2) - fmaxf(y1-0.5f*h1, y2-0.5f*h2);
    float inter = (cw > 0.f && ch > 0.f) ? cw*ch : 0.f;
    return inter / (w1*h1 + w2*h2 - inter);
}

__global__ void __launch_bounds__(256, 4)
k_fused(const float* __restrict__ out,
        const float* __restrict__ tgt,
        const float* __restrict__ anch,
        float* __restrict__ d_out)
{
    __shared__ float    st[MAXT*12];
    __shared__ float4   s_lh[MAXT];
    __shared__ float    s_ga[MAXT];
    __shared__ int      s_flat[MAXT];
    __shared__ int      s_cls[MAXT];
    __shared__ float    s_anc[6];
    __shared__ float    s_gm;
    __shared__ int      s_cnt;
    __shared__ unsigned s_m0, s_m1;
    __shared__ float    s_gmp[2];
    __shared__ double   s_wsum[8];

    int tid = threadIdx.x;
    if (tid < 6) s_anc[tid] = anch[tid];
    double local = 0.0;

    if (blockIdx.x < DBLKS) {
        // ============ dense role: noobj loss, coalesced 4-cell groups ============
        int b    = blockIdx.x >> 3;
        int part = blockIdx.x & 7;

        bool pos = false;
        if (tid < MAXT) {
            const float* p = tgt + b*MAXT*12 + tid*12;
            float x = p[1], y = p[2];
            float gw = p[10]*NETWH, gh = p[11]*NETWH;
            float gx = x*(float)NWW, gy = y*(float)NHH;
            s_lh[tid] = make_float4(gx-0.5f*gw, gx+0.5f*gw, gy-0.5f*gh, gy+0.5f*gh);
            s_ga[tid] = gw*gh;
            pos = (x > 0.f);
        }
        if (tid < 64) {
            unsigned bal = __ballot_sync(0xFFFFFFFFu, pos);
            if ((tid & 31) == 0) { if (tid < 32) s_m0 = bal; else s_m1 = bal; }
        }
        __syncthreads();
        int cnt = (~s_m0) ? (__ffs(~s_m0) - 1) : (32 + __ffs(~s_m1) - 1);
        if (cnt > MAXT) cnt = MAXT;
        // warp-parallel min of GT areas (replaces serial thread-0 loop)
        if (tid < 64) {
            float a = (tid < cnt) ? s_ga[tid] : 1e30f;
            #pragma unroll
            for (int off = 16; off > 0; off >>= 1)
                a = fminf(a, __shfl_down_sync(0xFFFFFFFFu, a, off));
            if ((tid & 31) == 0) s_gmp[tid >> 5] = a;
        }
        __syncthreads();
        float gm = fminf(s_gmp[0], s_gmp[1]);

        // phase 1: gather up to 3 groups' loads (9 independent LDG.128)
        bool   act[3];
        float4 v9[3], v10[3], v11[3];
        const float* bp[3];
        int    remv[3];
        float  awv[3], ahv[3];
        #pragma unroll
        for (int k = 0; k < 3; k++) {
            int rg = tid + k*256;
            int g  = part*GPBLK + rg;
            bool a_ok = (rg < GPBLK) && (g < GPB_TOT);
            act[k] = a_ok;
            int cell0 = g * 4;
            int a   = (cell0 >= 2*NPIX) ? 2 : (cell0 >= NPIX ? 1 : 0);
            int rem = cell0 - a*NPIX;
            const float* basep = out + (size_t)(b*NANC + a)*NCH*NPIX + rem;
            bp[k] = basep; remv[k] = rem;
            awv[k] = s_anc[2*a]; ahv[k] = s_anc[2*a+1];
            if (a_ok) {
                v9[k]  = __ldcs(reinterpret_cast<const float4*>(basep + 9*NPIX));
                v10[k] = __ldcs(reinterpret_cast<const float4*>(basep + 10*NPIX));
                v11[k] = __ldcs(reinterpret_cast<const float4*>(basep + 11*NPIX));
            }
        }

        // phase 2: compute
        float lf = 0.f;
        #pragma unroll
        for (int k = 0; k < 3; k++) {
            if (!act[k]) continue;
            float a9[4]  = {v9[k].x,  v9[k].y,  v9[k].z,  v9[k].w};
            float a10[4] = {v10[k].x, v10[k].y, v10[k].z, v10[k].w};
            float a11[4] = {v11[k].x, v11[k].y, v11[k].z, v11[k].w};
            float awah = awv[k]*ahv[k];
            #pragma unroll
            for (int s = 0; s < 4; s++) {
                float o9 = a9[s], o10 = a10[s], o11 = a11[s];
                float pa_gate = awah * __expf(o9 + o10);
                bool ig = false;
                if (2.f*pa_gate > 0.99f*gm) {
                    float o0 = bp[k][s];
                    float o1 = bp[k][NPIX + s];
                    int cell = remv[k] + s;
                    int j = cell / NWW;
                    int i = cell - j*NWW;
                    ig = cell_ignored(o0, o1, o9, o10, awv[k], ahv[k], i, j,
                                      cnt, s_lh, s_ga);
                }
                if (!ig) lf += softplusf(o11);
            }
        }
        local = (double)lf;
    } else {
        // ============ target role: obj-cell losses for one batch ============
        int b = blockIdx.x - DBLKS;
        for (int i = tid; i < MAXT*12; i += 256) st[i] = tgt[b*MAXT*12 + i];
        __syncthreads();

        int t = tid;
        bool pos = (t < MAXT) && (st[t*12 + 1] > 0.f);
        if (t < 64) {
            unsigned bal = __ballot_sync(0xFFFFFFFFu, pos);
            if ((t & 31) == 0) { if (t < 32) s_m0 = bal; else s_m1 = bal; }
        }
        __syncthreads();
        int cnt = (~s_m0) ? (__ffs(~s_m0) - 1) : (32 + __ffs(~s_m1) - 1);
        if (cnt > MAXT) cnt = MAXT;

        float gx=0, gy=0, gw=0, gh=0, aw=0, ah=0;
        int best=0, gi=0, gj=0, flat=-1;
        if (t < MAXT) {
            const float* tb = st + t*12;
            gx = tb[1]*(float)NWW;  gy = tb[2]*(float)NHH;
            gw = tb[10]*NETWH;      gh = tb[11]*NETWH;
            s_ga[t] = gw*gh;
            s_lh[t] = make_float4(gx-0.5f*gw, gx+0.5f*gw, gy-0.5f*gh, gy+0.5f*gh);
            if (t < cnt) {
                float bestr = -1.f;
                #pragma unroll
                for (int a = 0; a < NANC; a++) {
                    float aw_ = s_anc[2*a], ah_ = s_anc[2*a+1];
                    float inter = fminf(gw, aw_) * fminf(gh, ah_);
                    float r = inter / (gw*gh + aw_*ah_ - inter);
                    if (r > bestr) { bestr = r; best = a; }
                }
                gi = min(max((int)floorf(gx), 0), NWW-1);
                gj = min(max((int)floorf(gy), 0), NHH-1);
                flat = best*NPIX + gj*NWW + gi;
                aw = s_anc[2*best]; ah = s_anc[2*best+1];
            }
            s_flat[t] = flat;
            s_cls[t]  = (int)tb[0];
        }
        __syncthreads();
        if (t < 64) {
            float a = (t < cnt) ? s_ga[t] : 1e30f;
            #pragma unroll
            for (int off = 16; off > 0; off >>= 1)
                a = fminf(a, __shfl_down_sync(0xFFFFFFFFu, a, off));
            if ((t & 31) == 0) s_gmp[t >> 5] = a;
        }
        __syncthreads();
        float gm = fminf(s_gmp[0], s_gmp[1]);

        if (t < cnt) {
            bool winner = true; unsigned mask = 0;
            for (int t2 = 0; t2 < cnt; t2++) {
                if (s_flat[t2] == flat) {
                    if (t2 > t) winner = false;
                    mask |= 1u << s_cls[t2];
                }
            }
            if (winner) {
                const float* tb = st + t*12;
                const float* basep = out + (size_t)(b*NANC + best)*NCH*NPIX
                                         + (gj*NWW + gi);
                float o[12];
                #pragma unroll
                for (int c = 0; c < 12; c++) o[c] = basep[c*NPIX];
                float cl[NCLS];
                #pragma unroll
                for (int c = 0; c < NCLS; c++) cl[c] = basep[(NLV + c)*NPIX];

                float l = 0.f;
                float tx = gx - (float)gi, ty = gy - (float)gj;
                l += bce_logit(o[0], tx) + bce_logit(o[1], ty);
                float r9 = logf(gw/aw), r10 = logf(gh/ah);
                float d9 = o[9]-r9, d10 = o[10]-r10;
                l += d9*d9 + d10*d10;
                float d2 = o[2]-tb[3], d3 = o[3]-tb[4], d4 = o[4]-tb[5];
                float ss = d2*d2 + d3*d3 + d4*d4;
                float dis = sqrtf(ss);
                if (dis <= BETA_C) l += 0.5f*ss/BETA_C;
                else               l += fabsf(d2)+fabsf(d3)+fabsf(d4) - 0.5f*BETA_C;
                float nrm = fmaxf(sqrtf(o[5]*o[5]+o[6]*o[6]+o[7]*o[7]+o[8]*o[8]), 1e-12f);
                l += fabsf(o[5]/nrm - tb[6]) + fabsf(o[6]/nrm - tb[7])
                   + fabsf(o[7]/nrm - tb[8]) + fabsf(o[8]/nrm - tb[9]);
                float px = sigfast(o[0]) + (float)gi;
                float py = sigfast(o[1]) + (float)gj;
                float pw = __expf(o[9])*aw, ph = __expf(o[10])*ah;
                float iou_t = iou_div(gx, gy, gw, gh, px, py, pw, ph);
                l += bce_logit(o[11], iou_t);
                #pragma unroll
                for (int c = 0; c < NCLS; c++) {
                    float tt = ((mask >> c) & 1u) ? 1.f : 0.f;
                    l += bce_logit(cl[c], tt);
                }
                // subtract dense role's noobj contribution for this cell
                float pa_gate = aw*ah*__expf(o[9]+o[10]);
                bool ig = false;
                if (2.f*pa_gate > 0.99f*gm)
                    ig = cell_ignored(o[0], o[1], o[9], o[10], aw, ah, gi, gj,
                                      cnt, s_lh, s_ga);
                if (!ig) l -= softplusf(o[11]);
                local = (double)l;
            }
        }
    }

    // ============ common block reduction + last-block finalize ============
    #pragma unroll
    for (int off = 16; off > 0; off >>= 1)
        local += __shfl_down_sync(0xFFFFFFFFu, local, off);
    int lane = tid & 31, wid = tid >> 5;
    if (lane == 0) s_wsum[wid] = local;
    __syncthreads();
    if (tid == 0) {
        double bs = 0.0;
        #pragma unroll
        for (int w = 0; w < 8; w++) bs += s_wsum[w];
        atomicAdd(&g_acc, bs);
        __threadfence();
        unsigned old = atomicAdd(&g_done, 1u);
        if (old == NBLKS - 1) {
            double tot = atomicAdd(&g_acc, 0.0);   // ordered read
            d_out[0] = (float)(tot * (1.0/(double)NBATCH));
            g_acc = 0.0;                           // self-reset for graph replay
            __threadfence();
            g_done = 0u;
        }
    }
}

extern "C" void kernel_launch(void* const* d_in, const int* in_sizes, int n_in,
                              void* d_out, int out_size) {
    const float* out  = nullptr;
    const float* tgt  = nullptr;
    const float* anch = nullptr;
    for (int k = 0; k < n_in; k++) {
        if      (in_sizes[k] == NBATCH*NANC*NCH*NPIX) out  = (const float*)d_in[k];
        else if (in_sizes[k] == NBATCH*MAXT*NLV)      tgt  = (const float*)d_in[k];
        else if (in_sizes[k] == NANC*2)               anch = (const float*)d_in[k];
    }
    k_fused<<<NBLKS, 256>>>(out, tgt, anch, (float*)d_out);
}